// round 2
// baseline (speedup 1.0000x reference)
#include <cuda_runtime.h>
#include <cstdint>

#define BB 4
#define NP 8192
#define MP 2048          // NP/4
#define KNN 16
#define CIN 64
#define CO 128
#define CG 67            // 3 + CIN
#define CGP 68           // padded
#define EPSBN 1e-5
#define CSZ 4            // FPS cluster size (CTAs per batch)
#define FPT 4            // points per thread in FPS
#define FTH 512          // threads per FPS CTA  (FTH*FPT*CSZ == NP)

// ---------------- scratch (static device allocations are allowed) -------------
__device__ float  g_newp[BB * MP * 3];
__device__ float4 g_pts4[BB * NP];
__device__ int    g_nidx[BB * MP * KNN];
__device__ float  g_ymax[BB * MP * CO];
__device__ float  g_ymin[BB * MP * CO];
__device__ double g_sum[CO];
__device__ double g_sumsq[CO];
__device__ float  g_scale[CO];
__device__ float  g_meanv[CO];
__device__ float  g_shift[CO];

// ---------------- init: zero the BN accumulators (every replay) ----------------
__global__ void init_kernel() {
    int t = threadIdx.x;
    if (t < CO) { g_sum[t] = 0.0; g_sumsq[t] = 0.0; }
}

// ---------------- precompute (x,y,z,|p|^2) per point ---------------------------
__global__ void prep_kernel(const float* __restrict__ pt) {
    int i = blockIdx.x * 256 + threadIdx.x;
    if (i >= BB * NP) return;
    float x = pt[3 * i], y = pt[3 * i + 1], z = pt[3 * i + 2];
    // JAX: sum(p*p, -1) == (x*x + y*y) + z*z, no fma contraction
    float pp = __fadd_rn(__fadd_rn(__fmul_rn(x, x), __fmul_rn(y, y)), __fmul_rn(z, z));
    g_pts4[i] = make_float4(x, y, z, pp);
}

// ---------------- cluster helpers ----------------------------------------------
__device__ __forceinline__ uint32_t smem_u32(const void* p) {
    return (uint32_t)__cvta_generic_to_shared(p);
}
__device__ __forceinline__ uint32_t ctarank() {
    uint32_t r; asm("mov.u32 %0, %%cluster_ctarank;" : "=r"(r)); return r;
}
__device__ __forceinline__ uint32_t mapa_rank(uint32_t addr, uint32_t r) {
    uint32_t out;
    asm("mapa.shared::cluster.u32 %0, %1, %2;" : "=r"(out) : "r"(addr), "r"(r));
    return out;
}
__device__ __forceinline__ void st_clu_u64(uint32_t a, unsigned long long v) {
    asm volatile("st.shared::cluster.u64 [%0], %1;" :: "r"(a), "l"(v) : "memory");
}
__device__ __forceinline__ void st_clu_u32(uint32_t a, uint32_t v) {
    asm volatile("st.shared::cluster.u32 [%0], %1;" :: "r"(a), "r"(v) : "memory");
}
__device__ __forceinline__ void mbar_arrive_rel_cluster(uint32_t a) {
    asm volatile("mbarrier.arrive.release.cluster.shared::cluster.b64 _, [%0];"
                 :: "r"(a) : "memory");
}
__device__ __forceinline__ void mbar_wait_acq_cluster(uint32_t a, uint32_t parity) {
    asm volatile(
        "{\n\t"
        ".reg .pred P1;\n\t"
        "WAITL_%=:\n\t"
        "mbarrier.try_wait.parity.acquire.cluster.shared::cta.b64 P1, [%0], %1, 0x989680;\n\t"
        "@P1 bra.uni WAITD_%=;\n\t"
        "bra.uni WAITL_%=;\n\t"
        "WAITD_%=:\n\t"
        "}"
        :: "r"(a), "r"(parity) : "memory");
}

// ---------------- FPS: 4-CTA cluster per batch ----------------------------------
__global__ void __cluster_dims__(CSZ, 1, 1) __launch_bounds__(FTH, 1)
fps_kernel(const float* __restrict__ pt) {
    // CTA-local reduction scratch
    __shared__ float s_wv[FTH / 32];
    __shared__ int   s_wi[FTH / 32];
    __shared__ float s_wx[FTH / 32], s_wy[FTH / 32], s_wz[FTH / 32];
    // cluster exchange slots, double-buffered by iteration parity
    __shared__ __align__(8) unsigned long long s_key[2][CSZ];
    __shared__ __align__(8) unsigned long long s_xy[2][CSZ];
    __shared__ float s_z[2][CSZ];
    __shared__ __align__(8) unsigned long long s_mbar;

    const int t = threadIdx.x;
    const uint32_t r = ctarank();
    const int b = blockIdx.x / CSZ;
    const float* P = pt + (size_t)b * NP * 3;

    if (t == 0) {
        uint32_t mb = smem_u32(&s_mbar);
        asm volatile("mbarrier.init.shared.b64 [%0], %1;" :: "r"(mb), "r"(CSZ) : "memory");
    }
    __syncthreads();
    asm volatile("barrier.cluster.arrive.aligned;" ::: "memory");
    asm volatile("barrier.cluster.wait.aligned;" ::: "memory");

    // load my points
    float px[FPT], py[FPT], pz[FPT], dist[FPT];
    const int base = (int)r * (FTH * FPT) + t * FPT;
#pragma unroll
    for (int i = 0; i < FPT; i++) {
        int g = base + i;
        px[i] = P[3 * g]; py[i] = P[3 * g + 1]; pz[i] = P[3 * g + 2];
        dist[i] = 1e10f;
    }

    // initial query = point 0
    float qx = P[0], qy = P[1], qz = P[2];
    if (r == 0 && t == 0) {
        int o = (b * MP) * 3;
        g_newp[o] = qx; g_newp[o + 1] = qy; g_newp[o + 2] = qz;
    }

    const uint32_t mb_local = smem_u32(&s_mbar);
    const int lane = t & 31;
    const int wrp = t >> 5;

    for (int it = 1; it < MP; it++) {
        const int buf = it & 1;
        const uint32_t parity = (uint32_t)((it - 1) & 1);

        // per-thread compute + argmax (lowest idx wins ties via strict >)
        float bv = -1.0f; int bi = 0;
#pragma unroll
        for (int i = 0; i < FPT; i++) {
            float dx = __fsub_rn(px[i], qx);
            float dy = __fsub_rn(py[i], qy);
            float dz = __fsub_rn(pz[i], qz);
            float d = __fadd_rn(__fadd_rn(__fmul_rn(dx, dx), __fmul_rn(dy, dy)),
                                __fmul_rn(dz, dz));
            float nd = fminf(dist[i], d);
            dist[i] = nd;
            if (nd > bv) { bv = nd; bi = base + i; }
        }
        float bx = px[bi - base], by = py[bi - base], bz = pz[bi - base];

        // warp reduce (carry coords)
#pragma unroll
        for (int o = 16; o > 0; o >>= 1) {
            float ov = __shfl_down_sync(0xffffffffu, bv, o);
            int   oi = __shfl_down_sync(0xffffffffu, bi, o);
            float ox = __shfl_down_sync(0xffffffffu, bx, o);
            float oy = __shfl_down_sync(0xffffffffu, by, o);
            float oz = __shfl_down_sync(0xffffffffu, bz, o);
            if (ov > bv || (ov == bv && oi < bi)) {
                bv = ov; bi = oi; bx = ox; by = oy; bz = oz;
            }
        }
        if (lane == 0) {
            s_wv[wrp] = bv; s_wi[wrp] = bi;
            s_wx[wrp] = bx; s_wy[wrp] = by; s_wz[wrp] = bz;
        }
        __syncthreads();

        // stage 2: warp 0 reduces the 16 leader candidates, lane 0 exchanges
        if (wrp == 0) {
            float v; int idx; float x, y, z;
            if (lane < FTH / 32) {
                v = s_wv[lane]; idx = s_wi[lane];
                x = s_wx[lane]; y = s_wy[lane]; z = s_wz[lane];
            } else { v = -2.0f; idx = 0x7fffffff; x = 0.f; y = 0.f; z = 0.f; }
#pragma unroll
            for (int o = 8; o > 0; o >>= 1) {
                float ov = __shfl_down_sync(0xffffffffu, v, o);
                int   oi = __shfl_down_sync(0xffffffffu, idx, o);
                float ox = __shfl_down_sync(0xffffffffu, x, o);
                float oy = __shfl_down_sync(0xffffffffu, y, o);
                float oz = __shfl_down_sync(0xffffffffu, z, o);
                if (ov > v || (ov == v && oi < idx)) {
                    v = ov; idx = oi; x = ox; y = oy; z = oz;
                }
            }
            if (lane == 0) {
                // dist >= 0 -> float bits are order-preserving; ~idx -> lowest idx wins
                unsigned long long key =
                    ((unsigned long long)__float_as_uint(v) << 32) |
                    (unsigned long long)(~(uint32_t)idx);
                unsigned long long xy =
                    ((unsigned long long)__float_as_uint(y) << 32) |
                    (unsigned long long)__float_as_uint(x);
                uint32_t zb = __float_as_uint(z);
                uint32_t a_key = smem_u32(&s_key[buf][r]);
                uint32_t a_xy  = smem_u32(&s_xy[buf][r]);
                uint32_t a_z   = smem_u32(&s_z[buf][r]);
#pragma unroll
                for (uint32_t d = 0; d < CSZ; d++) {
                    st_clu_u64(mapa_rank(a_key, d), key);
                    st_clu_u64(mapa_rank(a_xy, d), xy);
                    st_clu_u32(mapa_rank(a_z, d), zb);
                }
#pragma unroll
                for (uint32_t d = 0; d < CSZ; d++)
                    mbar_arrive_rel_cluster(mapa_rank(mb_local, d));
            }
        }

        // wait for all 4 candidates, reduce redundantly in every thread
        mbar_wait_acq_cluster(mb_local, parity);
        unsigned long long bk = s_key[buf][0]; int br = 0;
#pragma unroll
        for (int d = 1; d < CSZ; d++) {
            unsigned long long k = s_key[buf][d];
            if (k > bk) { bk = k; br = d; }
        }
        unsigned long long xy = s_xy[buf][br];
        qx = __uint_as_float((uint32_t)xy);
        qy = __uint_as_float((uint32_t)(xy >> 32));
        qz = s_z[buf][br];

        if (r == 0 && t == 0) {
            int o = (b * MP + it) * 3;
            g_newp[o] = qx; g_newp[o + 1] = qy; g_newp[o + 2] = qz;
        }
    }

    asm volatile("barrier.cluster.arrive.aligned;" ::: "memory");
    asm volatile("barrier.cluster.wait.aligned;" ::: "memory");
}

// ---------------- KNN: thread-per-query, 16-entry register heap ----------------
#define KT 2048   // point tile
__global__ void __launch_bounds__(128) knn_kernel() {
    __shared__ __align__(16) float4 tile[KT];
    const int m = blockIdx.x * 128 + threadIdx.x;       // global query id
    const int b = m / MP;

    const float q0 = g_newp[3 * m], q1 = g_newp[3 * m + 1], q2 = g_newp[3 * m + 2];
    const float qq = __fadd_rn(__fadd_rn(__fmul_rn(q0, q0), __fmul_rn(q1, q1)),
                               __fmul_rn(q2, q2));

    float bd[KNN]; int bix[KNN];
#pragma unroll
    for (int s = 0; s < KNN; s++) { bd[s] = 3.402823466e38f; bix[s] = 0x7fffffff; }
    float wv = 3.402823466e38f; int wIdx = 0x7fffffff; int wslot = 0;

    const float4* src = g_pts4 + (size_t)b * NP;
    for (int tb = 0; tb < NP / KT; tb++) {
        for (int j = threadIdx.x; j < KT; j += 128) tile[j] = src[tb * KT + j];
        __syncthreads();
        for (int jj = 0; jj < KT; jj++) {
            float4 p = tile[jj];
            // JAX: d2 = (qq + pp) - 2*(q . p)  with fma-chain dot
            float dot = __fmaf_rn(q2, p.z, __fmaf_rn(q1, p.y, __fmul_rn(q0, p.x)));
            float d2 = __fsub_rn(__fadd_rn(qq, p.w), __fmul_rn(2.0f, dot));
            if (d2 < wv) {                        // strict: ties keep earlier index
                int j = tb * KT + jj;
#pragma unroll
                for (int s = 0; s < KNN; s++)
                    if (s == wslot) { bd[s] = d2; bix[s] = j; }
                wv = bd[0]; wIdx = bix[0]; wslot = 0;
#pragma unroll
                for (int s = 1; s < KNN; s++)
                    if (bd[s] > wv || (bd[s] == wv && bix[s] > wIdx)) {
                        wv = bd[s]; wIdx = bix[s]; wslot = s;
                    }
            }
        }
        __syncthreads();
    }
#pragma unroll
    for (int s = 0; s < KNN; s++) g_nidx[m * KNN + s] = bix[s];
}

// ---------------- group + linear + channel stats + k-max/min -------------------
__global__ void __launch_bounds__(128) group_kernel(const float* __restrict__ feat,
                                                    const float* __restrict__ Wm) {
    __shared__ __align__(16) float sW[CO * CG];
    __shared__ __align__(16) float sg[KNN][CGP];
    __shared__ int snb[KNN];

    const int tid = threadIdx.x;
    const int o = tid;
    for (int j = tid; j < CO * CG; j += 128) sW[j] = Wm[j];
    __syncthreads();

    float w[CGP];
#pragma unroll
    for (int c = 0; c < CG; c++) w[c] = sW[o * CG + c];
    w[CG] = 0.0f;

    double lsum = 0.0, lsq = 0.0;
    const int m0 = blockIdx.x * 8;

    for (int mi = 0; mi < 8; mi++) {
        const int m = m0 + mi;
        const int b = m / MP;
        if (tid < KNN) snb[tid] = g_nidx[m * KNN + tid];
        __syncthreads();

        // relative xyz (JAX-exact sub) + zero pad
        if (tid < KNN) {
            float4 p = g_pts4[(size_t)b * NP + snb[tid]];
            sg[tid][0] = __fsub_rn(p.x, g_newp[3 * m]);
            sg[tid][1] = __fsub_rn(p.y, g_newp[3 * m + 1]);
            sg[tid][2] = __fsub_rn(p.z, g_newp[3 * m + 2]);
            sg[tid][CG] = 0.0f;
        }
        // features: 16 rows x 64, 8 floats per thread
        {
            int k = tid >> 3, c0 = (tid & 7) << 3;
            const float* fr = feat + ((size_t)b * NP + snb[k]) * CIN + c0;
            float4 a = *(const float4*)fr;
            float4 bq = *(const float4*)(fr + 4);
            sg[k][3 + c0 + 0] = a.x;  sg[k][3 + c0 + 1] = a.y;
            sg[k][3 + c0 + 2] = a.z;  sg[k][3 + c0 + 3] = a.w;
            sg[k][3 + c0 + 4] = bq.x; sg[k][3 + c0 + 5] = bq.y;
            sg[k][3 + c0 + 6] = bq.z; sg[k][3 + c0 + 7] = bq.w;
        }
        __syncthreads();

        float ymx = -3.402823466e38f, ymn = 3.402823466e38f;
#pragma unroll 1
        for (int k = 0; k < KNN; k++) {
            const float4* gr = (const float4*)sg[k];
            float acc = 0.0f;
#pragma unroll
            for (int c4 = 0; c4 < CGP / 4; c4++) {
                float4 gv = gr[c4];
                acc = __fmaf_rn(gv.x, w[4 * c4 + 0], acc);
                acc = __fmaf_rn(gv.y, w[4 * c4 + 1], acc);
                acc = __fmaf_rn(gv.z, w[4 * c4 + 2], acc);
                acc = __fmaf_rn(gv.w, w[4 * c4 + 3], acc);
            }
            ymx = fmaxf(ymx, acc);
            ymn = fminf(ymn, acc);
            lsum += (double)acc;
            lsq = fma((double)acc, (double)acc, lsq);
        }
        g_ymax[m * CO + o] = ymx;
        g_ymin[m * CO + o] = ymn;
        __syncthreads();
    }
    atomicAdd(&g_sum[o], lsum);
    atomicAdd(&g_sumsq[o], lsq);
}

// ---------------- BN statistics finalize ----------------------------------------
__global__ void stats_kernel(const float* __restrict__ gamma,
                             const float* __restrict__ beta) {
    int o = threadIdx.x;
    if (o >= CO) return;
    const double n = (double)BB * MP * KNN;
    double mean = g_sum[o] / n;
    double var = g_sumsq[o] / n - mean * mean;
    if (var < 0.0) var = 0.0;
    double s = (double)gamma[o] / sqrt(var + EPSBN);
    g_scale[o] = (float)s;
    g_meanv[o] = (float)mean;
    g_shift[o] = beta[o];
}

// ---------------- output: relu(max_k BN(y)) via max/min trick -------------------
__global__ void out_kernel(float* __restrict__ dst) {
    int idx = blockIdx.x * 256 + threadIdx.x;
    if (idx >= BB * MP * CO) return;
    int o = idx & (CO - 1);
    float s = g_scale[o];
    float v = (s >= 0.0f) ? g_ymax[idx] : g_ymin[idx];
    float t = __fsub_rn(v, g_meanv[o]);
    float r = __fadd_rn(__fmul_rn(t, s), g_shift[o]);
    dst[idx] = fmaxf(r, 0.0f);
}

__global__ void copy_np_kernel(float* __restrict__ dst) {
    int i = blockIdx.x * 256 + threadIdx.x;
    if (i < BB * MP * 3) dst[i] = g_newp[i];
}

__global__ void splits_f32_kernel(float* __restrict__ dst) {
    int i = threadIdx.x;
    if (i <= BB) dst[i] = (float)(i * MP);
}
__global__ void splits_i64_kernel(long long* __restrict__ dst) {
    int i = threadIdx.x;
    if (i <= BB) dst[i] = (long long)i * MP;
}

// ---------------- launch ---------------------------------------------------------
extern "C" void kernel_launch(void* const* d_in, const int* in_sizes, int n_in,
                              void* d_out, int out_size) {
    const float* point = (const float*)d_in[0];
    const float* feat  = (const float*)d_in[1];
    const float* Wm    = (const float*)d_in[3];
    const float* gamma = (const float*)d_in[4];
    const float* beta  = (const float*)d_in[5];
    float* out = (float*)d_out;

    init_kernel<<<1, 128>>>();
    prep_kernel<<<(BB * NP + 255) / 256, 256>>>(point);
    fps_kernel<<<BB * CSZ, FTH>>>(point);
    knn_kernel<<<BB * MP / 128, 128>>>();
    group_kernel<<<BB * MP / 8, 128>>>(feat, Wm);
    stats_kernel<<<1, 128>>>(gamma, beta);

    const int NPT = BB * MP * 3;          // 24576
    const int NFT = BB * MP * CO;         // 1048576
    int feat_off = 0;
    bool write_pts = false;
    if (out_size >= NPT + NFT) { write_pts = true; feat_off = NPT; }

    out_kernel<<<(NFT + 255) / 256, 256>>>(out + feat_off);
    if (write_pts) copy_np_kernel<<<(NPT + 255) / 256, 256>>>(out);

    int rem = out_size - feat_off - NFT;
    if (rem == BB + 1) {
        splits_f32_kernel<<<1, 32>>>(out + feat_off + NFT);
    } else if (rem == 2 * (BB + 1)) {
        splits_i64_kernel<<<1, 32>>>((long long*)(out + feat_off + NFT));
    }
}

// round 3
// speedup vs baseline: 1.3075x; 1.3075x over previous
#include <cuda_runtime.h>
#include <cstdint>

#define BB 4
#define NP 8192
#define MP 2048          // NP/4
#define KNN 16
#define CIN 64
#define CO 128
#define CG 67            // 3 + CIN
#define CGP 68           // padded
#define EPSBN 1e-5
#define CSZ 8            // FPS cluster size (CTAs per batch)
#define FPT 2            // points per thread in FPS
#define FTH 512          // threads per FPS CTA  (FTH*FPT*CSZ == NP)
#define LPTS (FTH*FPT)   // points per CTA (1024)

// ---------------- scratch (static device allocations are allowed) -------------
__device__ float  g_newp[BB * MP * 3];
__device__ float4 g_pts4[BB * NP];
__device__ int    g_nidx[BB * MP * KNN];
__device__ float  g_ymax[BB * MP * CO];
__device__ float  g_ymin[BB * MP * CO];
__device__ double g_sum[CO];
__device__ double g_sumsq[CO];
__device__ float  g_scale[CO];
__device__ float  g_meanv[CO];
__device__ float  g_shift[CO];

// ---------------- init: zero the BN accumulators (every replay) ----------------
__global__ void init_kernel() {
    int t = threadIdx.x;
    if (t < CO) { g_sum[t] = 0.0; g_sumsq[t] = 0.0; }
}

// ---------------- precompute (x,y,z,|p|^2) per point ---------------------------
__global__ void prep_kernel(const float* __restrict__ pt) {
    int i = blockIdx.x * 256 + threadIdx.x;
    if (i >= BB * NP) return;
    float x = pt[3 * i], y = pt[3 * i + 1], z = pt[3 * i + 2];
    // JAX: sum(p*p, -1) == (x*x + y*y) + z*z, no fma contraction
    float pp = __fadd_rn(__fadd_rn(__fmul_rn(x, x), __fmul_rn(y, y)), __fmul_rn(z, z));
    g_pts4[i] = make_float4(x, y, z, pp);
}

// ---------------- cluster helpers ----------------------------------------------
__device__ __forceinline__ uint32_t smem_u32(const void* p) {
    return (uint32_t)__cvta_generic_to_shared(p);
}
__device__ __forceinline__ uint32_t ctarank() {
    uint32_t r; asm("mov.u32 %0, %%cluster_ctarank;" : "=r"(r)); return r;
}
__device__ __forceinline__ uint32_t mapa_rank(uint32_t addr, uint32_t r) {
    uint32_t out;
    asm("mapa.shared::cluster.u32 %0, %1, %2;" : "=r"(out) : "r"(addr), "r"(r));
    return out;
}
__device__ __forceinline__ void st_clu_u64(uint32_t a, unsigned long long v) {
    asm volatile("st.shared::cluster.u64 [%0], %1;" :: "r"(a), "l"(v) : "memory");
}
__device__ __forceinline__ void st_clu_u32(uint32_t a, uint32_t v) {
    asm volatile("st.shared::cluster.u32 [%0], %1;" :: "r"(a), "r"(v) : "memory");
}
__device__ __forceinline__ void st_clu_rel_u32(uint32_t a, uint32_t v) {
    asm volatile("st.release.cluster.shared::cluster.b32 [%0], %1;"
                 :: "r"(a), "r"(v) : "memory");
}
__device__ __forceinline__ uint32_t ld_acq_clu_u32(uint32_t a) {
    uint32_t v;
    asm volatile("ld.acquire.cluster.shared.b32 %0, [%1];" : "=r"(v) : "r"(a) : "memory");
    return v;
}

// exchange slot: 24 bytes
struct __align__(8) Slot {
    unsigned long long key;   // (distbits<<32) | ~idx  (max => furthest, lowest idx)
    float x, y, z;
    unsigned int tag;         // iteration number, release-stored last
};

// ---------------- FPS: 8-CTA cluster per batch ----------------------------------
__global__ void __cluster_dims__(CSZ, 1, 1) __launch_bounds__(FTH, 1)
fps_kernel() {
    __shared__ float sx[LPTS], sy[LPTS], sz[LPTS];
    __shared__ uint2 s_lead[FTH / 32];
    __shared__ Slot  s_slot[2][CSZ];

    const int t = threadIdx.x;
    const uint32_t r = ctarank();
    const int b = blockIdx.x / CSZ;
    const float4* P4 = g_pts4 + (size_t)b * NP;

    // init exchange tags
    if (t < 2 * CSZ) s_slot[t / CSZ][t % CSZ].tag = 0u;

    // load my points (registers + smem coord copy for winner lookup)
    float px[FPT], py[FPT], pz[FPT], dist[FPT];
    const int base = (int)r * LPTS + t * FPT;
#pragma unroll
    for (int i = 0; i < FPT; i++) {
        float4 v = P4[base + i];
        int li = t * FPT + i;
        px[i] = v.x; py[i] = v.y; pz[i] = v.z;
        sx[li] = v.x; sy[li] = v.y; sz[li] = v.z;
        dist[i] = 1e10f;
    }

    // initial query = point 0 of this batch
    float4 q0 = __ldg(P4);
    float qx = q0.x, qy = q0.y, qz = q0.z;
    if (r == 0 && t == 0) {
        int o = (b * MP) * 3;
        g_newp[o] = qx; g_newp[o + 1] = qy; g_newp[o + 2] = qz;
    }

    // destination addresses for my rank's slot in every CTA (lanes 0..CSZ-1 of warp 0)
    uint32_t a_dst0 = 0, a_dst1 = 0;
    if (t < CSZ) {
        a_dst0 = mapa_rank(smem_u32(&s_slot[0][r]), (uint32_t)t);
        a_dst1 = mapa_rank(smem_u32(&s_slot[1][r]), (uint32_t)t);
    }
    const uint32_t a_mytag0 = smem_u32(&s_slot[0][t < CSZ ? t : 0].tag);
    const uint32_t a_mytag1 = smem_u32(&s_slot[1][t < CSZ ? t : 0].tag);

    __syncthreads();
    asm volatile("barrier.cluster.arrive.aligned;" ::: "memory");
    asm volatile("barrier.cluster.wait.aligned;" ::: "memory");

    const int lane = t & 31;
    const int wrp = t >> 5;

    for (int it = 1; it < MP; it++) {
        const int buf = it & 1;

        // ---- per-thread distance update + local argmax (lowest idx on ties) ----
        float bv = -1.0f; int bi = 0;
#pragma unroll
        for (int i = 0; i < FPT; i++) {
            float dx = __fsub_rn(px[i], qx);
            float dy = __fsub_rn(py[i], qy);
            float dz = __fsub_rn(pz[i], qz);
            float d = __fadd_rn(__fadd_rn(__fmul_rn(dx, dx), __fmul_rn(dy, dy)),
                                __fmul_rn(dz, dz));
            float nd = fminf(dist[i], d);
            dist[i] = nd;
            if (nd > bv) { bv = nd; bi = base + i; }
        }

        // ---- warp argmax via REDUX (dist >= 0 so float bits are monotone;
        //      lane order == index order so lowest set lane = lowest idx) ----
        uint32_t mybits = __float_as_uint(bv);
        uint32_t mx = __reduce_max_sync(0xffffffffu, mybits);
        uint32_t ball = __ballot_sync(0xffffffffu, mybits == mx);
        int wl = __ffs(ball) - 1;
        int wbi = __shfl_sync(0xffffffffu, bi, wl);
        if (lane == 0) s_lead[wrp] = make_uint2(mx, (uint32_t)wbi);
        __syncthreads();

        // ---- stage 2 in warp 0: reduce 16 leaders, ship candidate to all CTAs ----
        if (wrp == 0) {
            uint32_t bits2 = 0u, idx2 = 0u;
            if (lane < FTH / 32) { uint2 L = s_lead[lane]; bits2 = L.x; idx2 = L.y; }
            uint32_t m2 = __reduce_max_sync(0xffffffffu, bits2);
            uint32_t b2 = __ballot_sync(0xffffffffu, (bits2 == m2) && (lane < FTH / 32));
            int w2 = __ffs(b2) - 1;
            idx2 = __shfl_sync(0xffffffffu, idx2, w2);
            if (lane < CSZ) {
                int li = (int)idx2 - (int)r * LPTS;          // local index in this CTA
                float x = sx[li], y = sy[li], z = sz[li];
                unsigned long long key =
                    ((unsigned long long)m2 << 32) | (unsigned long long)(~idx2);
                unsigned long long xy =
                    ((unsigned long long)__float_as_uint(y) << 32) |
                    (unsigned long long)__float_as_uint(x);
                uint32_t a = buf ? a_dst1 : a_dst0;          // &slot in CTA 'lane'
                st_clu_u64(a, key);
                st_clu_u64(a + 8, xy);
                st_clu_u32(a + 16, __float_as_uint(z));
                st_clu_rel_u32(a + 20, (uint32_t)it);        // publish
            }
        }

        // ---- only CSZ threads poll; everyone else parks at the barrier ----
        if (t < CSZ) {
            uint32_t a = buf ? a_mytag1 : a_mytag0;
            while (ld_acq_clu_u32(a) != (uint32_t)it) { }
        }
        __syncthreads();

        // ---- reduce the CSZ candidates (redundantly in every thread) ----
        unsigned long long bk = s_slot[buf][0].key; int br = 0;
#pragma unroll
        for (int d = 1; d < CSZ; d++) {
            unsigned long long k = s_slot[buf][d].key;
            if (k > bk) { bk = k; br = d; }
        }
        qx = s_slot[buf][br].x;
        qy = s_slot[buf][br].y;
        qz = s_slot[buf][br].z;

        if (r == 0 && t == 0) {
            int o = (b * MP + it) * 3;
            g_newp[o] = qx; g_newp[o + 1] = qy; g_newp[o + 2] = qz;
        }
    }

    asm volatile("barrier.cluster.arrive.aligned;" ::: "memory");
    asm volatile("barrier.cluster.wait.aligned;" ::: "memory");
}

// ---------------- KNN: thread-per-query, 16-entry register heap ----------------
#define KT 2048   // point tile
__global__ void __launch_bounds__(128) knn_kernel() {
    __shared__ __align__(16) float4 tile[KT];
    const int m = blockIdx.x * 128 + threadIdx.x;       // global query id
    const int b = m / MP;

    const float q0 = g_newp[3 * m], q1 = g_newp[3 * m + 1], q2 = g_newp[3 * m + 2];
    const float qq = __fadd_rn(__fadd_rn(__fmul_rn(q0, q0), __fmul_rn(q1, q1)),
                               __fmul_rn(q2, q2));

    float bd[KNN]; int bix[KNN];
#pragma unroll
    for (int s = 0; s < KNN; s++) { bd[s] = 3.402823466e38f; bix[s] = 0x7fffffff; }
    float wv = 3.402823466e38f; int wIdx = 0x7fffffff; int wslot = 0;

    const float4* src = g_pts4 + (size_t)b * NP;
    for (int tb = 0; tb < NP / KT; tb++) {
        for (int j = threadIdx.x; j < KT; j += 128) tile[j] = src[tb * KT + j];
        __syncthreads();
        for (int jj = 0; jj < KT; jj++) {
            float4 p = tile[jj];
            // JAX: d2 = (qq + pp) - 2*(q . p)  with fma-chain dot
            float dot = __fmaf_rn(q2, p.z, __fmaf_rn(q1, p.y, __fmul_rn(q0, p.x)));
            float d2 = __fsub_rn(__fadd_rn(qq, p.w), __fmul_rn(2.0f, dot));
            if (d2 < wv) {                        // strict: ties keep earlier index
                int j = tb * KT + jj;
#pragma unroll
                for (int s = 0; s < KNN; s++)
                    if (s == wslot) { bd[s] = d2; bix[s] = j; }
                wv = bd[0]; wIdx = bix[0]; wslot = 0;
#pragma unroll
                for (int s = 1; s < KNN; s++)
                    if (bd[s] > wv || (bd[s] == wv && bix[s] > wIdx)) {
                        wv = bd[s]; wIdx = bix[s]; wslot = s;
                    }
            }
        }
        __syncthreads();
    }
#pragma unroll
    for (int s = 0; s < KNN; s++) g_nidx[m * KNN + s] = bix[s];
}

// ---------------- group + linear + channel stats + k-max/min -------------------
__global__ void __launch_bounds__(128) group_kernel(const float* __restrict__ feat,
                                                    const float* __restrict__ Wm) {
    __shared__ __align__(16) float sW[CO * CG];
    __shared__ __align__(16) float sg[KNN][CGP];
    __shared__ int snb[KNN];

    const int tid = threadIdx.x;
    const int o = tid;
    for (int j = tid; j < CO * CG; j += 128) sW[j] = Wm[j];
    __syncthreads();

    float w[CGP];
#pragma unroll
    for (int c = 0; c < CG; c++) w[c] = sW[o * CG + c];
    w[CG] = 0.0f;

    double lsum = 0.0, lsq = 0.0;
    const int m0 = blockIdx.x * 8;

    for (int mi = 0; mi < 8; mi++) {
        const int m = m0 + mi;
        const int b = m / MP;
        if (tid < KNN) snb[tid] = g_nidx[m * KNN + tid];
        __syncthreads();

        // relative xyz (JAX-exact sub) + zero pad
        if (tid < KNN) {
            float4 p = g_pts4[(size_t)b * NP + snb[tid]];
            sg[tid][0] = __fsub_rn(p.x, g_newp[3 * m]);
            sg[tid][1] = __fsub_rn(p.y, g_newp[3 * m + 1]);
            sg[tid][2] = __fsub_rn(p.z, g_newp[3 * m + 2]);
            sg[tid][CG] = 0.0f;
        }
        // features: 16 rows x 64, 8 floats per thread
        {
            int k = tid >> 3, c0 = (tid & 7) << 3;
            const float* fr = feat + ((size_t)b * NP + snb[k]) * CIN + c0;
            float4 a = *(const float4*)fr;
            float4 bq = *(const float4*)(fr + 4);
            sg[k][3 + c0 + 0] = a.x;  sg[k][3 + c0 + 1] = a.y;
            sg[k][3 + c0 + 2] = a.z;  sg[k][3 + c0 + 3] = a.w;
            sg[k][3 + c0 + 4] = bq.x; sg[k][3 + c0 + 5] = bq.y;
            sg[k][3 + c0 + 6] = bq.z; sg[k][3 + c0 + 7] = bq.w;
        }
        __syncthreads();

        float ymx = -3.402823466e38f, ymn = 3.402823466e38f;
#pragma unroll 1
        for (int k = 0; k < KNN; k++) {
            const float4* gr = (const float4*)sg[k];
            float acc = 0.0f;
#pragma unroll
            for (int c4 = 0; c4 < CGP / 4; c4++) {
                float4 gv = gr[c4];
                acc = __fmaf_rn(gv.x, w[4 * c4 + 0], acc);
                acc = __fmaf_rn(gv.y, w[4 * c4 + 1], acc);
                acc = __fmaf_rn(gv.z, w[4 * c4 + 2], acc);
                acc = __fmaf_rn(gv.w, w[4 * c4 + 3], acc);
            }
            ymx = fmaxf(ymx, acc);
            ymn = fminf(ymn, acc);
            lsum += (double)acc;
            lsq = fma((double)acc, (double)acc, lsq);
        }
        g_ymax[m * CO + o] = ymx;
        g_ymin[m * CO + o] = ymn;
        __syncthreads();
    }
    atomicAdd(&g_sum[o], lsum);
    atomicAdd(&g_sumsq[o], lsq);
}

// ---------------- BN statistics finalize ----------------------------------------
__global__ void stats_kernel(const float* __restrict__ gamma,
                             const float* __restrict__ beta) {
    int o = threadIdx.x;
    if (o >= CO) return;
    const double n = (double)BB * MP * KNN;
    double mean = g_sum[o] / n;
    double var = g_sumsq[o] / n - mean * mean;
    if (var < 0.0) var = 0.0;
    double s = (double)gamma[o] / sqrt(var + EPSBN);
    g_scale[o] = (float)s;
    g_meanv[o] = (float)mean;
    g_shift[o] = beta[o];
}

// ---------------- output: relu(max_k BN(y)) via max/min trick -------------------
__global__ void out_kernel(float* __restrict__ dst) {
    int idx = blockIdx.x * 256 + threadIdx.x;
    if (idx >= BB * MP * CO) return;
    int o = idx & (CO - 1);
    float s = g_scale[o];
    float v = (s >= 0.0f) ? g_ymax[idx] : g_ymin[idx];
    float t = __fsub_rn(v, g_meanv[o]);
    float r = __fadd_rn(__fmul_rn(t, s), g_shift[o]);
    dst[idx] = fmaxf(r, 0.0f);
}

__global__ void copy_np_kernel(float* __restrict__ dst) {
    int i = blockIdx.x * 256 + threadIdx.x;
    if (i < BB * MP * 3) dst[i] = g_newp[i];
}

__global__ void splits_f32_kernel(float* __restrict__ dst) {
    int i = threadIdx.x;
    if (i <= BB) dst[i] = (float)(i * MP);
}
__global__ void splits_i64_kernel(long long* __restrict__ dst) {
    int i = threadIdx.x;
    if (i <= BB) dst[i] = (long long)i * MP;
}

// ---------------- launch ---------------------------------------------------------
extern "C" void kernel_launch(void* const* d_in, const int* in_sizes, int n_in,
                              void* d_out, int out_size) {
    const float* point = (const float*)d_in[0];
    const float* feat  = (const float*)d_in[1];
    const float* Wm    = (const float*)d_in[3];
    const float* gamma = (const float*)d_in[4];
    const float* beta  = (const float*)d_in[5];
    float* out = (float*)d_out;

    init_kernel<<<1, 128>>>();
    prep_kernel<<<(BB * NP + 255) / 256, 256>>>(point);
    fps_kernel<<<BB * CSZ, FTH>>>();
    knn_kernel<<<BB * MP / 128, 128>>>();
    group_kernel<<<BB * MP / 8, 128>>>(feat, Wm);
    stats_kernel<<<1, 128>>>(gamma, beta);

    const int NPT = BB * MP * 3;          // 24576
    const int NFT = BB * MP * CO;         // 1048576
    int feat_off = 0;
    bool write_pts = false;
    if (out_size >= NPT + NFT) { write_pts = true; feat_off = NPT; }

    out_kernel<<<(NFT + 255) / 256, 256>>>(out + feat_off);
    if (write_pts) copy_np_kernel<<<(NPT + 255) / 256, 256>>>(out);

    int rem = out_size - feat_off - NFT;
    if (rem == BB + 1) {
        splits_f32_kernel<<<1, 32>>>(out + feat_off + NFT);
    } else if (rem == 2 * (BB + 1)) {
        splits_i64_kernel<<<1, 32>>>((long long*)(out + feat_off + NFT));
    }
}

// round 4
// speedup vs baseline: 1.7541x; 1.3416x over previous
#include <cuda_runtime.h>
#include <cstdint>

#define BB 4
#define NP 8192
#define MP 2048          // NP/4
#define KNN 16
#define CIN 64
#define CO 128
#define CG 67            // 3 + CIN
#define CGP 68           // padded
#define EPSBN 1e-5
#define FPT 8            // points per thread in FPS (1024 threads * 8 = 8192)

// ---------------- scratch (static device allocations are allowed) -------------
__device__ float  g_newp[BB * MP * 3];
__device__ float4 g_pts4[BB * NP];
__device__ int    g_nidx[BB * MP * KNN];
__device__ float  g_ymax[BB * MP * CO];
__device__ float  g_ymin[BB * MP * CO];
__device__ double g_sum[CO];
__device__ double g_sumsq[CO];
__device__ float  g_scale[CO];
__device__ float  g_meanv[CO];
__device__ float  g_shift[CO];

// ---------------- init: zero the BN accumulators (every replay) ----------------
__global__ void init_kernel() {
    int t = threadIdx.x;
    if (t < CO) { g_sum[t] = 0.0; g_sumsq[t] = 0.0; }
}

// ---------------- precompute (x,y,z,|p|^2) per point ---------------------------
__global__ void prep_kernel(const float* __restrict__ pt) {
    int i = blockIdx.x * 256 + threadIdx.x;
    if (i >= BB * NP) return;
    float x = pt[3 * i], y = pt[3 * i + 1], z = pt[3 * i + 2];
    // JAX: sum(p*p, -1) == (x*x + y*y) + z*z, no fma contraction
    float pp = __fadd_rn(__fadd_rn(__fmul_rn(x, x), __fmul_rn(y, y)), __fmul_rn(z, z));
    g_pts4[i] = make_float4(x, y, z, pp);
}

// ---------------- packed f32x2 helpers (bit-exact .rn per-lane ops) -------------
__device__ __forceinline__ unsigned long long f32x2_pack(float lo, float hi) {
    unsigned long long r;
    asm("mov.b64 %0, {%1, %2};" : "=l"(r) : "f"(lo), "f"(hi));
    return r;
}
__device__ __forceinline__ unsigned long long f32x2_add(unsigned long long a,
                                                        unsigned long long b) {
    unsigned long long r;
    asm("add.rn.f32x2 %0, %1, %2;" : "=l"(r) : "l"(a), "l"(b));
    return r;
}
__device__ __forceinline__ unsigned long long f32x2_mul(unsigned long long a,
                                                        unsigned long long b) {
    unsigned long long r;
    asm("mul.rn.f32x2 %0, %1, %2;" : "=l"(r) : "l"(a), "l"(b));
    return r;
}
__device__ __forceinline__ void f32x2_unpack(unsigned long long v, float& lo, float& hi) {
    asm("mov.b64 {%0, %1}, %2;" : "=f"(lo), "=f"(hi) : "l"(v));
}

// ---------------- FPS: one CTA per batch, packed math + REDUX argmax ------------
extern __shared__ float fps_sm[];   // sx[NP], sy[NP], sz[NP]  (96 KB)
__global__ void __launch_bounds__(1024, 1) fps_kernel() {
    float* sx = fps_sm;
    float* sy = fps_sm + NP;
    float* sz = fps_sm + 2 * NP;
    __shared__ uint2 s_lead[2][32];

    const int t = threadIdx.x;
    const int b = blockIdx.x;
    const float4* P4 = g_pts4 + (size_t)b * NP;
    const int base = t * FPT;

    // stage coords: registers (packed pairs) + smem copy for winner lookup
    unsigned long long pxp[FPT / 2], pyp[FPT / 2], pzp[FPT / 2];
    float dist[FPT];
    {
        float tx[FPT], ty[FPT], tz[FPT];
#pragma unroll
        for (int i = 0; i < FPT; i++) {
            float4 v = P4[base + i];
            tx[i] = v.x; ty[i] = v.y; tz[i] = v.z;
            sx[base + i] = v.x; sy[base + i] = v.y; sz[base + i] = v.z;
            dist[i] = 1e10f;
        }
#pragma unroll
        for (int j = 0; j < FPT / 2; j++) {
            pxp[j] = f32x2_pack(tx[2 * j], tx[2 * j + 1]);
            pyp[j] = f32x2_pack(ty[2 * j], ty[2 * j + 1]);
            pzp[j] = f32x2_pack(tz[2 * j], tz[2 * j + 1]);
        }
    }

    float4 q0 = __ldg(P4);
    float qx = q0.x, qy = q0.y, qz = q0.z;
    if (t == 0) {
        int o = (b * MP) * 3;
        g_newp[o] = qx; g_newp[o + 1] = qy; g_newp[o + 2] = qz;
    }
    __syncthreads();

    const int lane = t & 31;
    const int wrp = t >> 5;

    for (int it = 1; it < MP; it++) {
        const int buf = it & 1;
        // negate q once: p - q == p + (-q) bit-exact
        const unsigned long long nqx2 = f32x2_pack(-qx, -qx);
        const unsigned long long nqy2 = f32x2_pack(-qy, -qy);
        const unsigned long long nqz2 = f32x2_pack(-qz, -qz);

        float bv = -1.0f; int bi = 0;
#pragma unroll
        for (int j = 0; j < FPT / 2; j++) {
            // JAX-exact per lane: d = ((dx*dx + dy*dy) + dz*dz)
            unsigned long long dx = f32x2_add(pxp[j], nqx2);
            unsigned long long dy = f32x2_add(pyp[j], nqy2);
            unsigned long long dz = f32x2_add(pzp[j], nqz2);
            unsigned long long t1 = f32x2_mul(dx, dx);
            unsigned long long t2 = f32x2_mul(dy, dy);
            unsigned long long s1 = f32x2_add(t1, t2);
            unsigned long long t3 = f32x2_mul(dz, dz);
            unsigned long long dd = f32x2_add(s1, t3);
            float d0, d1;
            f32x2_unpack(dd, d0, d1);
            float n0 = fminf(dist[2 * j], d0);
            dist[2 * j] = n0;
            if (n0 > bv) { bv = n0; bi = base + 2 * j; }       // strict >: lowest idx on tie
            float n1 = fminf(dist[2 * j + 1], d1);
            dist[2 * j + 1] = n1;
            if (n1 > bv) { bv = n1; bi = base + 2 * j + 1; }
        }

        // warp argmax: dist >= 0 -> float bits monotone; lane order == index order
        uint32_t mybits = __float_as_uint(bv);
        uint32_t mx = __reduce_max_sync(0xffffffffu, mybits);
        uint32_t ball = __ballot_sync(0xffffffffu, mybits == mx);
        int wbi = __shfl_sync(0xffffffffu, bi, __ffs(ball) - 1);
        if (lane == 0) s_lead[buf][wrp] = make_uint2(mx, (uint32_t)wbi);
        __syncthreads();

        // every warp reduces the 32 leaders itself (no second barrier)
        uint2 L = s_lead[buf][lane];
        uint32_t m2 = __reduce_max_sync(0xffffffffu, L.x);
        uint32_t b2 = __ballot_sync(0xffffffffu, L.x == m2);
        int w = __shfl_sync(0xffffffffu, (int)L.y, __ffs(b2) - 1);

        qx = sx[w]; qy = sy[w]; qz = sz[w];          // broadcast LDS
        if (t == 0) {
            int o = (b * MP + it) * 3;
            g_newp[o] = qx; g_newp[o + 1] = qy; g_newp[o + 2] = qz;
        }
    }
}

// ---------------- KNN: thread-per-query, 16-entry register heap ----------------
#define KT 2048   // point tile
__global__ void __launch_bounds__(128) knn_kernel() {
    __shared__ __align__(16) float4 tile[KT];
    const int m = blockIdx.x * 128 + threadIdx.x;       // global query id
    const int b = m / MP;

    const float q0 = g_newp[3 * m], q1 = g_newp[3 * m + 1], q2 = g_newp[3 * m + 2];
    const float qq = __fadd_rn(__fadd_rn(__fmul_rn(q0, q0), __fmul_rn(q1, q1)),
                               __fmul_rn(q2, q2));

    float bd[KNN]; int bix[KNN];
#pragma unroll
    for (int s = 0; s < KNN; s++) { bd[s] = 3.402823466e38f; bix[s] = 0x7fffffff; }
    float wv = 3.402823466e38f; int wIdx = 0x7fffffff; int wslot = 0;

    const float4* src = g_pts4 + (size_t)b * NP;
    for (int tb = 0; tb < NP / KT; tb++) {
        for (int j = threadIdx.x; j < KT; j += 128) tile[j] = src[tb * KT + j];
        __syncthreads();
        for (int jj = 0; jj < KT; jj++) {
            float4 p = tile[jj];
            // JAX: d2 = (qq + pp) - 2*(q . p)  with fma-chain dot
            float dot = __fmaf_rn(q2, p.z, __fmaf_rn(q1, p.y, __fmul_rn(q0, p.x)));
            float d2 = __fsub_rn(__fadd_rn(qq, p.w), __fmul_rn(2.0f, dot));
            if (d2 < wv) {                        // strict: ties keep earlier index
                int j = tb * KT + jj;
#pragma unroll
                for (int s = 0; s < KNN; s++)
                    if (s == wslot) { bd[s] = d2; bix[s] = j; }
                wv = bd[0]; wIdx = bix[0]; wslot = 0;
#pragma unroll
                for (int s = 1; s < KNN; s++)
                    if (bd[s] > wv || (bd[s] == wv && bix[s] > wIdx)) {
                        wv = bd[s]; wIdx = bix[s]; wslot = s;
                    }
            }
        }
        __syncthreads();
    }
#pragma unroll
    for (int s = 0; s < KNN; s++) g_nidx[m * KNN + s] = bix[s];
}

// ---------------- group + linear + channel stats + k-max/min -------------------
__global__ void __launch_bounds__(128) group_kernel(const float* __restrict__ feat,
                                                    const float* __restrict__ Wm) {
    __shared__ __align__(16) float sW[CO * CG];
    __shared__ __align__(16) float sg[KNN][CGP];
    __shared__ int snb[KNN];

    const int tid = threadIdx.x;
    const int o = tid;
    for (int j = tid; j < CO * CG; j += 128) sW[j] = Wm[j];
    __syncthreads();

    float w[CGP];
#pragma unroll
    for (int c = 0; c < CG; c++) w[c] = sW[o * CG + c];
    w[CG] = 0.0f;

    double lsum = 0.0, lsq = 0.0;
    const int m0 = blockIdx.x * 8;

    for (int mi = 0; mi < 8; mi++) {
        const int m = m0 + mi;
        const int b = m / MP;
        if (tid < KNN) snb[tid] = g_nidx[m * KNN + tid];
        __syncthreads();

        // relative xyz (JAX-exact sub) + zero pad
        if (tid < KNN) {
            float4 p = g_pts4[(size_t)b * NP + snb[tid]];
            sg[tid][0] = __fsub_rn(p.x, g_newp[3 * m]);
            sg[tid][1] = __fsub_rn(p.y, g_newp[3 * m + 1]);
            sg[tid][2] = __fsub_rn(p.z, g_newp[3 * m + 2]);
            sg[tid][CG] = 0.0f;
        }
        // features: 16 rows x 64, 8 floats per thread
        {
            int k = tid >> 3, c0 = (tid & 7) << 3;
            const float* fr = feat + ((size_t)b * NP + snb[k]) * CIN + c0;
            float4 a = *(const float4*)fr;
            float4 bq = *(const float4*)(fr + 4);
            sg[k][3 + c0 + 0] = a.x;  sg[k][3 + c0 + 1] = a.y;
            sg[k][3 + c0 + 2] = a.z;  sg[k][3 + c0 + 3] = a.w;
            sg[k][3 + c0 + 4] = bq.x; sg[k][3 + c0 + 5] = bq.y;
            sg[k][3 + c0 + 6] = bq.z; sg[k][3 + c0 + 7] = bq.w;
        }
        __syncthreads();

        float ymx = -3.402823466e38f, ymn = 3.402823466e38f;
#pragma unroll 1
        for (int k = 0; k < KNN; k++) {
            const float4* gr = (const float4*)sg[k];
            float acc = 0.0f;
#pragma unroll
            for (int c4 = 0; c4 < CGP / 4; c4++) {
                float4 gv = gr[c4];
                acc = __fmaf_rn(gv.x, w[4 * c4 + 0], acc);
                acc = __fmaf_rn(gv.y, w[4 * c4 + 1], acc);
                acc = __fmaf_rn(gv.z, w[4 * c4 + 2], acc);
                acc = __fmaf_rn(gv.w, w[4 * c4 + 3], acc);
            }
            ymx = fmaxf(ymx, acc);
            ymn = fminf(ymn, acc);
            lsum += (double)acc;
            lsq = fma((double)acc, (double)acc, lsq);
        }
        g_ymax[m * CO + o] = ymx;
        g_ymin[m * CO + o] = ymn;
        __syncthreads();
    }
    atomicAdd(&g_sum[o], lsum);
    atomicAdd(&g_sumsq[o], lsq);
}

// ---------------- BN statistics finalize ----------------------------------------
__global__ void stats_kernel(const float* __restrict__ gamma,
                             const float* __restrict__ beta) {
    int o = threadIdx.x;
    if (o >= CO) return;
    const double n = (double)BB * MP * KNN;
    double mean = g_sum[o] / n;
    double var = g_sumsq[o] / n - mean * mean;
    if (var < 0.0) var = 0.0;
    double s = (double)gamma[o] / sqrt(var + EPSBN);
    g_scale[o] = (float)s;
    g_meanv[o] = (float)mean;
    g_shift[o] = beta[o];
}

// ---------------- output: relu(max_k BN(y)) via max/min trick -------------------
__global__ void out_kernel(float* __restrict__ dst) {
    int idx = blockIdx.x * 256 + threadIdx.x;
    if (idx >= BB * MP * CO) return;
    int o = idx & (CO - 1);
    float s = g_scale[o];
    float v = (s >= 0.0f) ? g_ymax[idx] : g_ymin[idx];
    float t = __fsub_rn(v, g_meanv[o]);
    float r = __fadd_rn(__fmul_rn(t, s), g_shift[o]);
    dst[idx] = fmaxf(r, 0.0f);
}

__global__ void copy_np_kernel(float* __restrict__ dst) {
    int i = blockIdx.x * 256 + threadIdx.x;
    if (i < BB * MP * 3) dst[i] = g_newp[i];
}

__global__ void splits_f32_kernel(float* __restrict__ dst) {
    int i = threadIdx.x;
    if (i <= BB) dst[i] = (float)(i * MP);
}
__global__ void splits_i64_kernel(long long* __restrict__ dst) {
    int i = threadIdx.x;
    if (i <= BB) dst[i] = (long long)i * MP;
}

// ---------------- launch ---------------------------------------------------------
extern "C" void kernel_launch(void* const* d_in, const int* in_sizes, int n_in,
                              void* d_out, int out_size) {
    const float* point = (const float*)d_in[0];
    const float* feat  = (const float*)d_in[1];
    const float* Wm    = (const float*)d_in[3];
    const float* gamma = (const float*)d_in[4];
    const float* beta  = (const float*)d_in[5];
    float* out = (float*)d_out;

    const int FPS_SMEM = 3 * NP * 4;      // 96 KB dynamic
    cudaFuncSetAttribute(fps_kernel, cudaFuncAttributeMaxDynamicSharedMemorySize, FPS_SMEM);

    init_kernel<<<1, 128>>>();
    prep_kernel<<<(BB * NP + 255) / 256, 256>>>(point);
    fps_kernel<<<BB, 1024, FPS_SMEM>>>();
    knn_kernel<<<BB * MP / 128, 128>>>();
    group_kernel<<<BB * MP / 8, 128>>>(feat, Wm);
    stats_kernel<<<1, 128>>>(gamma, beta);

    const int NPT = BB * MP * 3;          // 24576
    const int NFT = BB * MP * CO;         // 1048576
    int feat_off = 0;
    bool write_pts = false;
    if (out_size >= NPT + NFT) { write_pts = true; feat_off = NPT; }

    out_kernel<<<(NFT + 255) / 256, 256>>>(out + feat_off);
    if (write_pts) copy_np_kernel<<<(NPT + 255) / 256, 256>>>(out);

    int rem = out_size - feat_off - NFT;
    if (rem == BB + 1) {
        splits_f32_kernel<<<1, 32>>>(out + feat_off + NFT);
    } else if (rem == 2 * (BB + 1)) {
        splits_i64_kernel<<<1, 32>>>((long long*)(out + feat_off + NFT));
    }
}